// round 15
// baseline (speedup 1.0000x reference)
#include <cuda_runtime.h>
#include <cuda_fp16.h>
#include <cstdint>

// Problem: B=2, H=16, S=2048, D=128, temperature=1. Output tuple = (O, attn).
constexpr int kS = 2048;
constexpr int kD = 128;
constexpr int kBH = 32;
constexpr int kQT = 64;             // q rows per CTA
constexpr int kKT = 64;             // keys per tile
constexpr int kTiles = kS / kKT;    // 32
constexpr int kThreads = 256;       // 8 warps: (row-group 0..3) x (half 0..1)
constexpr float kScaleLog2e = 0.08838834764831845f * 1.4426950408889634f;

// Preconverted fp16 K [bh][key][d] and transposed V [bh][d][key] (16MB each).
// uint4 type guarantees 16B alignment for cp.async.
__device__ uint4 g_kh4[(size_t)kBH * kS * kD / 8];
__device__ uint4 g_vth4[(size_t)kBH * kD * kS / 8];

// smem layout (bytes) — total 56KB -> 3 CTAs/SM
constexpr int SM_Q   = 0;          // 64x128 fp16 (256B/row, 16 chunks, swz ch^(r&7))
constexpr int SM_K   = 16384;      // 64x128 fp16, same layout
constexpr int SM_VT  = 32768;      // 128(d) x 64(key) fp16 (128B/row, 8 chunks)
constexpr int SM_P   = 49152;      // 64x64 fp16 (128B/row, 8 chunks)
constexpr int SM_TOTAL = 57344;
// post-loop aliases (P dead then):
constexpr int SM_RSUM = SM_P;          // 128 floats: [half][row]
constexpr int SM_INV  = SM_P + 512;    // 64 floats

__device__ __forceinline__ uint32_t smem_u32(const void* p) {
    uint32_t a;
    asm("{ .reg .u64 t; cvta.to.shared.u64 t, %1; cvt.u32.u64 %0, t; }" : "=r"(a) : "l"(p));
    return a;
}
__device__ __forceinline__ float ex2f(float x) {
    float y; asm("ex2.approx.f32 %0, %1;" : "=f"(y) : "f"(x)); return y;
}

#define CP_ASYNC16(dst, src) \
    asm volatile("cp.async.cg.shared.global [%0], [%1], 16;" :: "r"(dst), "l"(src))
#define CP_COMMIT()  asm volatile("cp.async.commit_group;")
#define CP_WAIT0()   asm volatile("cp.async.wait_group 0;" ::: "memory")

#define LDSM4(r, addr) \
    asm volatile("ldmatrix.sync.aligned.m8n8.x4.shared.b16 {%0,%1,%2,%3}, [%4];" \
        : "=r"((r)[0]), "=r"((r)[1]), "=r"((r)[2]), "=r"((r)[3]) : "r"(addr))

#define MMA(c, a, b0_, b1_) \
    asm volatile("mma.sync.aligned.m16n8k16.row.col.f32.f16.f16.f32 " \
        "{%0,%1,%2,%3}, {%4,%5,%6,%7}, {%8,%9}, {%0,%1,%2,%3};" \
        : "+f"((c)[0]), "+f"((c)[1]), "+f"((c)[2]), "+f"((c)[3]) \
        : "r"((a)[0]), "r"((a)[1]), "r"((a)[2]), "r"((a)[3]), "r"(b0_), "r"(b1_))

__device__ __forceinline__ uint32_t pack2h(float a, float b) {
    __half2 t = __floats2half2_rn(a, b);
    return reinterpret_cast<const uint32_t&>(t);
}
__device__ __forceinline__ uint2 pack4h(float x, float y, float z, float w) {
    return make_uint2(pack2h(x, y), pack2h(z, w));
}

#define STS64(addr, v) \
    asm volatile("st.shared.v2.u32 [%0], {%1, %2};" :: "r"(addr), "r"((v).x), "r"((v).y))
#define LDS64(v, addr) \
    asm volatile("ld.shared.v2.u32 {%0, %1}, [%2];" : "=r"((v).x), "=r"((v).y) : "r"(addr))

// ---- prep: K fp32 -> fp16 [bh][key][d]; V fp32 -> fp16 transposed [bh][d][key] ----
__global__ __launch_bounds__(256, 4)
void sdpa_prep_kernel(const float* __restrict__ K, const float* __restrict__ V) {
    const int tid = threadIdx.x;
    const int k0 = blockIdx.x * kKT;
    const int bh = blockIdx.y;
    const float* Kg = K + (size_t)bh * kS * kD;
    const float* Vg = V + (size_t)bh * kS * kD;
    uint2* kh2 = (uint2*)g_kh4;
    uint2* vth2 = (uint2*)g_vth4;

    // K: coalesced fp32 read -> coalesced 8B fp16 write
    #pragma unroll
    for (int it = 0; it < 8; it++) {
        int idx = it * 256 + tid;
        int r = idx >> 5, c4 = idx & 31;
        float4 v = *(const float4*)(Kg + (size_t)(k0 + r) * kD + c4 * 4);
        kh2[((size_t)bh * kS + k0 + r) * (kD / 4) + c4] = pack4h(v.x, v.y, v.z, v.w);
    }
    // V: coalesced fp32 row reads -> transposed 8B fp16 writes
    #pragma unroll
    for (int it = 0; it < 8; it++) {
        int idx = it * 256 + tid;
        int d = idx & 127, kq = idx >> 7;   // kq 0..15 (4 keys each)
        const float* vp = Vg + (size_t)(k0 + kq * 4) * kD + d;
        vth2[((size_t)bh * kD + d) * (kS / 4) + (k0 >> 2) + kq] =
            pack4h(vp[0], vp[kD], vp[2 * kD], vp[3 * kD]);
    }
}

__global__ __launch_bounds__(kThreads, 3)
void sdpa_mma_kernel(const float* __restrict__ Q, const int* __restrict__ mask,
                     float* __restrict__ outO, float* __restrict__ outA) {
    extern __shared__ char sm8[];
    const uint32_t smb = smem_u32(sm8);
    const int tid = threadIdx.x;
    const int wid = tid >> 5, lane = tid & 31;
    const int bh = blockIdx.y;
    const int q0 = blockIdx.x * kQT;
    const int rw = wid & 3, h = wid >> 2;   // row-group / half
    const int r0 = rw * 16;                 // warp's q rows [r0, r0+16)
    const int kh = h * 32;                  // warp's key half (S phase)
    const int g  = lane >> 2;
    const int qt = lane & 3;
    const int lrow = lane & 15, lsel = lane >> 4;

    const float* Qg = Q + ((size_t)bh * kS + q0) * kD;
    const char* khB  = (const char*)g_kh4 + (size_t)bh * kS * kD * 2;
    const char* vthB = (const char*)g_vth4 + (size_t)bh * kD * kS * 2;

    // ---- prologue: load Q (prescaled, fp16), float4-granular ----
    #pragma unroll
    for (int it = 0; it < 8; it++) {
        int idx = it * kThreads + tid;
        int r = idx >> 5, c4 = idx & 31;
        float4 v = *(const float4*)(Qg + (size_t)r * kD + c4 * 4);
        uint2 hv = pack4h(v.x * kScaleLog2e, v.y * kScaleLog2e,
                          v.z * kScaleLog2e, v.w * kScaleLog2e);
        uint32_t a = smb + SM_Q +
            (uint32_t)(r * 256 + ((((c4 >> 1) ^ (r & 7))) << 4) + (c4 & 1) * 8);
        STS64(a, hv);
    }

    float oacc[8][4];
    #pragma unroll
    for (int i = 0; i < 8; i++)
        #pragma unroll
        for (int j = 0; j < 4; j++) oacc[i][j] = 0.0f;
    float sum0 = 0.0f, sum1 = 0.0f;

    for (int kt = 0; kt < kTiles; kt++) {
        const int k0 = kt * kKT;

        __syncthreads();   // prev tile's reads of K/Vt/P done

        // ---- K tile: cp.async fp16 gmem -> swizzled smem (4 x 16B / thread) ----
        #pragma unroll
        for (int it = 0; it < 4; it++) {
            int idx = it * kThreads + tid;
            int r = idx >> 4, ch = idx & 15;       // 64 rows x 16 chunks
            CP_ASYNC16(smb + SM_K + (uint32_t)(r * 256 + ((ch ^ (r & 7)) << 4)),
                       khB + ((size_t)(k0 + r) * kD + ch * 8) * 2);
        }
        // ---- Vt tile: cp.async fp16 gmem (transposed) -> swizzled smem ----
        #pragma unroll
        for (int it = 0; it < 4; it++) {
            int idx = it * kThreads + tid;
            int d = idx >> 3, ch = idx & 7;        // 128 rows x 8 chunks
            CP_ASYNC16(smb + SM_VT + (uint32_t)(d * 128 + ((ch ^ (d & 7)) << 4)),
                       vthB + ((size_t)d * kS + k0 + ch * 8) * 2);
        }
        CP_COMMIT();
        CP_WAIT0();
        __syncthreads();   // K/Vt ready

        // ---- S = Q @ K^T : warp computes 16q x 32keys (pure fp16) ----
        float sacc[4][4];
        #pragma unroll
        for (int i = 0; i < 4; i++)
            #pragma unroll
            for (int j = 0; j < 4; j++) sacc[i][j] = 0.0f;

        #pragma unroll
        for (int c = 0; c < 8; c++) {
            uint32_t af[4];
            {
                int ar = r0 + lrow;
                int ac = 2 * c + lsel;
                uint32_t qa = smb + SM_Q + (uint32_t)(ar * 256 + ((ac ^ (ar & 7)) << 4));
                LDSM4(af, qa);
            }
            #pragma unroll
            for (int np = 0; np < 2; np++) {
                int br = kh + np * 16 + lrow;
                int bc = 2 * c + lsel;
                uint32_t kb = smb + SM_K + (uint32_t)(br * 256 + ((bc ^ (br & 7)) << 4));
                uint32_t bf[4];
                LDSM4(bf, kb);
                MMA(sacc[2 * np],     af, bf[0], bf[2]);
                MMA(sacc[2 * np + 1], af, bf[1], bf[3]);
            }
        }

        // ---- epilogue: mask (inline) + ex2 + rowsums + P -> smem (no gmem) ----
        {
            const int row_lo = q0 + r0 + g;
            const int cb = k0 + kh + qt * 2;
            const int* m_lo = mask + (size_t)row_lo * kS + cb;
            const int* m_hi = m_lo + (size_t)8 * kS;
            #pragma unroll
            for (int nt = 0; nt < 4; nt++) {
                int2 m0 = *(const int2*)(m_lo + nt * 8);
                int2 m1 = *(const int2*)(m_hi + nt * 8);
                float p0 = m0.x ? ex2f(sacc[nt][0]) : 0.0f;
                float p1 = m0.y ? ex2f(sacc[nt][1]) : 0.0f;
                float p2 = m1.x ? ex2f(sacc[nt][2]) : 0.0f;
                float p3 = m1.y ? ex2f(sacc[nt][3]) : 0.0f;
                sum0 += p0 + p1;
                sum1 += p2 + p3;
                uint32_t h0 = pack2h(p0, p1);
                uint32_t h1 = pack2h(p2, p3);
                uint32_t a0 = smb + SM_P +
                    (uint32_t)((r0 + g) * 128 + (((h * 4 + nt) ^ g) << 4) + 4 * qt);
                asm volatile("st.shared.b32 [%0], %1;" :: "r"(a0), "r"(h0));
                asm volatile("st.shared.b32 [%0], %1;" :: "r"(a0 + 8 * 128), "r"(h1));
            }
        }
        __syncthreads();   // P complete (cross-warp exchange)

        // ---- O += P @ Vt^T : warp computes 16q x 64d (pure fp16) ----
        #pragma unroll
        for (int kc = 0; kc < 4; kc++) {
            uint32_t af[4];
            {
                int ar = r0 + lrow;
                int ac = kc * 2 + lsel;
                uint32_t pa = smb + SM_P + (uint32_t)(ar * 128 + ((ac ^ (ar & 7)) << 4));
                LDSM4(af, pa);
            }
            #pragma unroll
            for (int np = 0; np < 4; np++) {
                int br = h * 64 + np * 16 + lrow;
                int bc = kc * 2 + lsel;
                uint32_t vb = smb + SM_VT + (uint32_t)(br * 128 + ((bc ^ (br & 7)) << 4));
                uint32_t bf[4];
                LDSM4(bf, vb);
                MMA(oacc[2 * np],     af, bf[0], bf[2]);
                MMA(oacc[2 * np + 1], af, bf[1], bf[3]);
            }
        }

        // ---- attn tile: coalesced write from P smem (fp16 -> fp32) ----
        {
            float* abase = outA + ((size_t)bh * kS + q0) * kS + k0;
            #pragma unroll
            for (int it = 0; it < 4; it++) {
                int idx = it * kThreads + tid;
                int r = idx >> 4, q4 = idx & 15;
                uint32_t pa = smb + SM_P +
                    (uint32_t)(r * 128 + ((((q4 >> 1) ^ (r & 7))) << 4) + (q4 & 1) * 8);
                uint2 hv;
                LDS64(hv, pa);
                __half2 h0 = *reinterpret_cast<__half2*>(&hv.x);
                __half2 h1 = *reinterpret_cast<__half2*>(&hv.y);
                float2 f0 = __half22float2(h0);
                float2 f1 = __half22float2(h1);
                *(float4*)(abase + (size_t)r * kS + q4 * 4) =
                    make_float4(f0.x, f0.y, f1.x, f1.y);
            }
        }
    }

    // ---- finalize: rowsums (per key-half partials), combine, normalize ----
    __syncthreads();   // all PV/copy reads of P done; safe to alias RSUM/INV
    sum0 += __shfl_xor_sync(0xffffffffu, sum0, 1);
    sum0 += __shfl_xor_sync(0xffffffffu, sum0, 2);
    sum1 += __shfl_xor_sync(0xffffffffu, sum1, 1);
    sum1 += __shfl_xor_sync(0xffffffffu, sum1, 2);
    float* rsum = (float*)(sm8 + SM_RSUM);
    if (qt == 0) {
        rsum[h * 64 + r0 + g]     = sum0;
        rsum[h * 64 + r0 + g + 8] = sum1;
    }
    __syncthreads();
    float* invp = (float*)(sm8 + SM_INV);
    if (tid < 64) invp[tid] = 1.0f / (rsum[tid] + rsum[64 + tid]);
    __syncthreads();

    const int row_lo = q0 + r0 + g, row_hi = row_lo + 8;
    float inv0 = invp[r0 + g], inv1 = invp[r0 + g + 8];
    float* o_lo = outO + ((size_t)bh * kS + row_lo) * kD + h * 64 + qt * 2;
    float* o_hi = outO + ((size_t)bh * kS + row_hi) * kD + h * 64 + qt * 2;
    #pragma unroll
    for (int nt = 0; nt < 8; nt++) {
        *(float2*)(o_lo + nt * 8) = make_float2(oacc[nt][0] * inv0, oacc[nt][1] * inv0);
        *(float2*)(o_hi + nt * 8) = make_float2(oacc[nt][2] * inv1, oacc[nt][3] * inv1);
    }

    // ---- tail: normalize this CTA's 64-row attn slab ----
    float* abase = outA + ((size_t)bh * kS + q0) * kS;
    #pragma unroll 4
    for (int i = 0; i < 128; i++) {
        int idx = i * kThreads + tid;
        int r = idx >> 9, c = idx & 511;
        float inv = invp[r];
        float4* p = (float4*)(abase + (size_t)r * kS) + c;
        float4 v = *p;
        v.x *= inv; v.y *= inv; v.z *= inv; v.w *= inv;
        *p = v;
    }
}

extern "C" void kernel_launch(void* const* d_in, const int* in_sizes, int n_in,
                              void* d_out, int out_size) {
    const float* Q    = (const float*)d_in[0];
    const float* K    = (const float*)d_in[1];
    const float* V    = (const float*)d_in[2];
    const int*   mask = (const int*)d_in[3];

    float* outO = (float*)d_out;
    float* outA = outO + (size_t)kBH * kS * kD;   // tuple order: (output, attn)

    cudaFuncSetAttribute(sdpa_mma_kernel, cudaFuncAttributeMaxDynamicSharedMemorySize, SM_TOTAL);

    dim3 pgrid(kS / kKT, kBH);
    sdpa_prep_kernel<<<pgrid, 256>>>(K, V);

    dim3 grid(kS / kQT, kBH);
    sdpa_mma_kernel<<<grid, kThreads, SM_TOTAL>>>(Q, mask, outO, outA);
}

// round 16
// speedup vs baseline: 1.2773x; 1.2773x over previous
#include <cuda_runtime.h>
#include <cuda_fp16.h>
#include <cstdint>

// Problem: B=2, H=16, S=2048, D=128, temperature=1. Output tuple = (O, attn).
constexpr int kS = 2048;
constexpr int kD = 128;
constexpr int kBH = 32;
constexpr int kQT = 64;             // q rows per CTA
constexpr int kKT = 64;             // keys per tile
constexpr int kTiles = kS / kKT;    // 32
constexpr int kThreads = 256;       // 8 warps: (row-group 0..3) x (half 0..1)
constexpr float kScaleLog2e = 0.08838834764831845f * 1.4426950408889634f;

// Preconverted fp16 K [bh][key][d] and transposed V [bh][d][key] (16MB each).
__device__ uint4 g_kh4[(size_t)kBH * kS * kD / 8];
__device__ uint4 g_vth4[(size_t)kBH * kD * kS / 8];

// smem layout (bytes) — total 56KB -> 3 CTAs/SM
constexpr int SM_Q   = 0;          // 64x128 fp16 (256B/row, 16 chunks, swz ch^(r&7))
constexpr int SM_K   = 16384;      // 64x128 fp16, same layout
constexpr int SM_VT  = 32768;      // 128(d) x 64(key) fp16 (128B/row, 8 chunks)
constexpr int SM_P   = 49152;      // 64x64 fp16 (128B/row, 8 chunks)
constexpr int SM_TOTAL = 57344;
// post-loop aliases (P dead then):
constexpr int SM_RSUM = SM_P;          // 128 floats: [half][row]
constexpr int SM_INV  = SM_P + 512;    // 64 floats

__device__ __forceinline__ uint32_t smem_u32(const void* p) {
    uint32_t a;
    asm("{ .reg .u64 t; cvta.to.shared.u64 t, %1; cvt.u32.u64 %0, t; }" : "=r"(a) : "l"(p));
    return a;
}
__device__ __forceinline__ float ex2f(float x) {
    float y; asm("ex2.approx.f32 %0, %1;" : "=f"(y) : "f"(x)); return y;
}

#define LDSM4(r, addr) \
    asm volatile("ldmatrix.sync.aligned.m8n8.x4.shared.b16 {%0,%1,%2,%3}, [%4];" \
        : "=r"((r)[0]), "=r"((r)[1]), "=r"((r)[2]), "=r"((r)[3]) : "r"(addr))

#define MMA(c, a, b0_, b1_) \
    asm volatile("mma.sync.aligned.m16n8k16.row.col.f32.f16.f16.f32 " \
        "{%0,%1,%2,%3}, {%4,%5,%6,%7}, {%8,%9}, {%0,%1,%2,%3};" \
        : "+f"((c)[0]), "+f"((c)[1]), "+f"((c)[2]), "+f"((c)[3]) \
        : "r"((a)[0]), "r"((a)[1]), "r"((a)[2]), "r"((a)[3]), "r"(b0_), "r"(b1_))

__device__ __forceinline__ uint32_t pack2h(float a, float b) {
    __half2 t = __floats2half2_rn(a, b);
    return reinterpret_cast<const uint32_t&>(t);
}
__device__ __forceinline__ uint2 pack4h(float x, float y, float z, float w) {
    return make_uint2(pack2h(x, y), pack2h(z, w));
}

#define STS64(addr, v) \
    asm volatile("st.shared.v2.u32 [%0], {%1, %2};" :: "r"(addr), "r"((v).x), "r"((v).y))
#define STS128(addr, v) \
    asm volatile("st.shared.v4.u32 [%0], {%1, %2, %3, %4};" \
        :: "r"(addr), "r"((v).x), "r"((v).y), "r"((v).z), "r"((v).w))
#define LDS64(v, addr) \
    asm volatile("ld.shared.v2.u32 {%0, %1}, [%2];" : "=r"((v).x), "=r"((v).y) : "r"(addr))

// ---- prep: K fp32 -> fp16 [bh][key][d]; V fp32 -> fp16 transposed [bh][d][key] ----
__global__ __launch_bounds__(256, 4)
void sdpa_prep_kernel(const float* __restrict__ K, const float* __restrict__ V) {
    const int tid = threadIdx.x;
    const int k0 = blockIdx.x * kKT;
    const int bh = blockIdx.y;
    const float* Kg = K + (size_t)bh * kS * kD;
    const float* Vg = V + (size_t)bh * kS * kD;
    uint2* kh2 = (uint2*)g_kh4;
    uint2* vth2 = (uint2*)g_vth4;

    #pragma unroll
    for (int it = 0; it < 8; it++) {
        int idx = it * 256 + tid;
        int r = idx >> 5, c4 = idx & 31;
        float4 v = *(const float4*)(Kg + (size_t)(k0 + r) * kD + c4 * 4);
        kh2[((size_t)bh * kS + k0 + r) * (kD / 4) + c4] = pack4h(v.x, v.y, v.z, v.w);
    }
    #pragma unroll
    for (int it = 0; it < 8; it++) {
        int idx = it * 256 + tid;
        int d = idx & 127, kq = idx >> 7;   // kq 0..15 (4 keys each)
        const float* vp = Vg + (size_t)(k0 + kq * 4) * kD + d;
        vth2[((size_t)bh * kD + d) * (kS / 4) + (k0 >> 2) + kq] =
            pack4h(vp[0], vp[kD], vp[2 * kD], vp[3 * kD]);
    }
}

__global__ __launch_bounds__(kThreads, 3)
void sdpa_mma_kernel(const float* __restrict__ Q, const int* __restrict__ mask,
                     float* __restrict__ outO, float* __restrict__ outA) {
    extern __shared__ char sm8[];
    const uint32_t smb = smem_u32(sm8);
    const int tid = threadIdx.x;
    const int wid = tid >> 5, lane = tid & 31;
    const int bh = blockIdx.y;
    const int q0 = blockIdx.x * kQT;
    const int rw = wid & 3, h = wid >> 2;   // row-group / half
    const int r0 = rw * 16;                 // warp's q rows [r0, r0+16)
    const int kh = h * 32;                  // warp's key half (S phase)
    const int g  = lane >> 2;
    const int qt = lane & 3;
    const int lrow = lane & 15, lsel = lane >> 4;

    const float* Qg = Q + ((size_t)bh * kS + q0) * kD;
    const char* khB  = (const char*)g_kh4 + (size_t)bh * kS * kD * 2;
    const char* vthB = (const char*)g_vth4 + (size_t)bh * kD * kS * 2;

    // ---- prologue: load Q (prescaled, fp16), float4-granular ----
    #pragma unroll
    for (int it = 0; it < 8; it++) {
        int idx = it * kThreads + tid;
        int r = idx >> 5, c4 = idx & 31;
        float4 v = *(const float4*)(Qg + (size_t)r * kD + c4 * 4);
        uint2 hv = pack4h(v.x * kScaleLog2e, v.y * kScaleLog2e,
                          v.z * kScaleLog2e, v.w * kScaleLog2e);
        uint32_t a = smb + SM_Q +
            (uint32_t)(r * 256 + ((((c4 >> 1) ^ (r & 7))) << 4) + (c4 & 1) * 8);
        STS64(a, hv);
    }

    float oacc[8][4];
    #pragma unroll
    for (int i = 0; i < 8; i++)
        #pragma unroll
        for (int j = 0; j < 4; j++) oacc[i][j] = 0.0f;
    float sum0 = 0.0f, sum1 = 0.0f;

    for (int kt = 0; kt < kTiles; kt++) {
        const int k0 = kt * kKT;

        __syncthreads();   // prev tile's reads of K/Vt/P done

        // ---- K tile: LDG.128 fp16 -> STS.128 swizzled (4 per thread) ----
        #pragma unroll
        for (int it = 0; it < 4; it++) {
            int idx = it * kThreads + tid;
            int r = idx >> 4, ch = idx & 15;       // 64 rows x 16 chunks
            uint4 v = *(const uint4*)(khB + ((size_t)(k0 + r) * kD + ch * 8) * 2);
            STS128(smb + SM_K + (uint32_t)(r * 256 + ((ch ^ (r & 7)) << 4)), v);
        }
        // ---- Vt tile: LDG.128 fp16 (transposed layout) -> STS.128 swizzled ----
        #pragma unroll
        for (int it = 0; it < 4; it++) {
            int idx = it * kThreads + tid;
            int d = idx >> 3, ch = idx & 7;        // 128 rows x 8 chunks
            uint4 v = *(const uint4*)(vthB + ((size_t)d * kS + k0 + ch * 8) * 2);
            STS128(smb + SM_VT + (uint32_t)(d * 128 + ((ch ^ (d & 7)) << 4)), v);
        }
        __syncthreads();   // K/Vt ready

        // ---- S = Q @ K^T : warp computes 16q x 32keys (pure fp16) ----
        float sacc[4][4];
        #pragma unroll
        for (int i = 0; i < 4; i++)
            #pragma unroll
            for (int j = 0; j < 4; j++) sacc[i][j] = 0.0f;

        #pragma unroll
        for (int c = 0; c < 8; c++) {
            uint32_t af[4];
            {
                int ar = r0 + lrow;
                int ac = 2 * c + lsel;
                uint32_t qa = smb + SM_Q + (uint32_t)(ar * 256 + ((ac ^ (ar & 7)) << 4));
                LDSM4(af, qa);
            }
            #pragma unroll
            for (int np = 0; np < 2; np++) {
                int br = kh + np * 16 + lrow;
                int bc = 2 * c + lsel;
                uint32_t kb = smb + SM_K + (uint32_t)(br * 256 + ((bc ^ (br & 7)) << 4));
                uint32_t bf[4];
                LDSM4(bf, kb);
                MMA(sacc[2 * np],     af, bf[0], bf[2]);
                MMA(sacc[2 * np + 1], af, bf[1], bf[3]);
            }
        }

        // ---- epilogue: mask (inline) + ex2 + rowsums + P -> smem (no gmem) ----
        {
            const int row_lo = q0 + r0 + g;
            const int cb = k0 + kh + qt * 2;
            const int* m_lo = mask + (size_t)row_lo * kS + cb;
            const int* m_hi = m_lo + (size_t)8 * kS;
            #pragma unroll
            for (int nt = 0; nt < 4; nt++) {
                int2 m0 = *(const int2*)(m_lo + nt * 8);
                int2 m1 = *(const int2*)(m_hi + nt * 8);
                float p0 = m0.x ? ex2f(sacc[nt][0]) : 0.0f;
                float p1 = m0.y ? ex2f(sacc[nt][1]) : 0.0f;
                float p2 = m1.x ? ex2f(sacc[nt][2]) : 0.0f;
                float p3 = m1.y ? ex2f(sacc[nt][3]) : 0.0f;
                sum0 += p0 + p1;
                sum1 += p2 + p3;
                uint32_t h0 = pack2h(p0, p1);
                uint32_t h1 = pack2h(p2, p3);
                uint32_t a0 = smb + SM_P +
                    (uint32_t)((r0 + g) * 128 + (((h * 4 + nt) ^ g) << 4) + 4 * qt);
                asm volatile("st.shared.b32 [%0], %1;" :: "r"(a0), "r"(h0));
                asm volatile("st.shared.b32 [%0], %1;" :: "r"(a0 + 8 * 128), "r"(h1));
            }
        }
        __syncthreads();   // P complete (cross-warp exchange)

        // ---- O += P @ Vt^T : warp computes 16q x 64d (pure fp16) ----
        #pragma unroll
        for (int kc = 0; kc < 4; kc++) {
            uint32_t af[4];
            {
                int ar = r0 + lrow;
                int ac = kc * 2 + lsel;
                uint32_t pa = smb + SM_P + (uint32_t)(ar * 128 + ((ac ^ (ar & 7)) << 4));
                LDSM4(af, pa);
            }
            #pragma unroll
            for (int np = 0; np < 4; np++) {
                int br = h * 64 + np * 16 + lrow;
                int bc = kc * 2 + lsel;
                uint32_t vb = smb + SM_VT + (uint32_t)(br * 128 + ((bc ^ (br & 7)) << 4));
                uint32_t bf[4];
                LDSM4(bf, vb);
                MMA(oacc[2 * np],     af, bf[0], bf[2]);
                MMA(oacc[2 * np + 1], af, bf[1], bf[3]);
            }
        }

        // ---- attn tile: coalesced write from P smem (fp16 -> fp32) ----
        {
            float* abase = outA + ((size_t)bh * kS + q0) * kS + k0;
            #pragma unroll
            for (int it = 0; it < 4; it++) {
                int idx = it * kThreads + tid;
                int r = idx >> 4, q4 = idx & 15;
                uint32_t pa = smb + SM_P +
                    (uint32_t)(r * 128 + ((((q4 >> 1) ^ (r & 7))) << 4) + (q4 & 1) * 8);
                uint2 hv;
                LDS64(hv, pa);
                __half2 h0 = *reinterpret_cast<__half2*>(&hv.x);
                __half2 h1 = *reinterpret_cast<__half2*>(&hv.y);
                float2 f0 = __half22float2(h0);
                float2 f1 = __half22float2(h1);
                *(float4*)(abase + (size_t)r * kS + q4 * 4) =
                    make_float4(f0.x, f0.y, f1.x, f1.y);
            }
        }
    }

    // ---- finalize: rowsums (per key-half partials), combine, normalize ----
    __syncthreads();   // all PV/copy reads of P done; safe to alias RSUM/INV
    sum0 += __shfl_xor_sync(0xffffffffu, sum0, 1);
    sum0 += __shfl_xor_sync(0xffffffffu, sum0, 2);
    sum1 += __shfl_xor_sync(0xffffffffu, sum1, 1);
    sum1 += __shfl_xor_sync(0xffffffffu, sum1, 2);
    float* rsum = (float*)(sm8 + SM_RSUM);
    if (qt == 0) {
        rsum[h * 64 + r0 + g]     = sum0;
        rsum[h * 64 + r0 + g + 8] = sum1;
    }
    __syncthreads();
    float* invp = (float*)(sm8 + SM_INV);
    if (tid < 64) invp[tid] = 1.0f / (rsum[tid] + rsum[64 + tid]);
    __syncthreads();

    const int row_lo = q0 + r0 + g, row_hi = row_lo + 8;
    float inv0 = invp[r0 + g], inv1 = invp[r0 + g + 8];
    float* o_lo = outO + ((size_t)bh * kS + row_lo) * kD + h * 64 + qt * 2;
    float* o_hi = outO + ((size_t)bh * kS + row_hi) * kD + h * 64 + qt * 2;
    #pragma unroll
    for (int nt = 0; nt < 8; nt++) {
        *(float2*)(o_lo + nt * 8) = make_float2(oacc[nt][0] * inv0, oacc[nt][1] * inv0);
        *(float2*)(o_hi + nt * 8) = make_float2(oacc[nt][2] * inv1, oacc[nt][3] * inv1);
    }

    // ---- tail: normalize this CTA's 64-row attn slab ----
    float* abase = outA + ((size_t)bh * kS + q0) * kS;
    #pragma unroll 4
    for (int i = 0; i < 128; i++) {
        int idx = i * kThreads + tid;
        int r = idx >> 9, c = idx & 511;
        float inv = invp[r];
        float4* p = (float4*)(abase + (size_t)r * kS) + c;
        float4 v = *p;
        v.x *= inv; v.y *= inv; v.z *= inv; v.w *= inv;
        *p = v;
    }
}

extern "C" void kernel_launch(void* const* d_in, const int* in_sizes, int n_in,
                              void* d_out, int out_size) {
    const float* Q    = (const float*)d_in[0];
    const float* K    = (const float*)d_in[1];
    const float* V    = (const float*)d_in[2];
    const int*   mask = (const int*)d_in[3];

    float* outO = (float*)d_out;
    float* outA = outO + (size_t)kBH * kS * kD;   // tuple order: (output, attn)

    cudaFuncSetAttribute(sdpa_mma_kernel, cudaFuncAttributeMaxDynamicSharedMemorySize, SM_TOTAL);

    dim3 pgrid(kS / kKT, kBH);
    sdpa_prep_kernel<<<pgrid, 256>>>(K, V);

    dim3 grid(kS / kQT, kBH);
    sdpa_mma_kernel<<<grid, kThreads, SM_TOTAL>>>(Q, mask, outO, outA);
}